// round 10
// baseline (speedup 1.0000x reference)
#include <cuda_runtime.h>
#include <cstdint>

// Problem constants
#define SDIM   64
#define CIN    16
#define COUTC  16
#define BATCH  4

// Tiling (R8 shape: 16 couts per block, 4 per thread, 8 x per thread)
#define TY         4
#define TXT        8
#define XPT        8
#define CPT        4
#define NTHREADS 128

// Padded input scratch: [b*16+cin][pz 66][py 66][px 68], zero borders
#define PX 68
#define PY 66
#define PZ 66
#define PPLANE   (PY * PX)            // 4488
#define PCHAN    (PZ * PPLANE)        // 296208
#define PAD_TOTAL ((size_t)BATCH * CIN * PCHAN)   // 18,957,312 floats

__device__ __align__(16) float g_pad[PAD_TOTAL];

// Transposed weights: [(cin*3+kd)*3+kh][kw*16 + cout]
#define WT_ELEMS (CIN * 9 * 48)
__device__ __align__(16) float g_wt[WT_ELEMS];

#define PACKF2(d, lo, hi) \
    asm("mov.b64 %0, {%1, %2};" : "=l"(d) : "f"(lo), "f"(hi))
#define FMAF2(d, a, b, c) \
    asm("fma.rn.f32x2 %0, %1, %2, %3;" : "=l"(d) : "l"(a), "l"(b), "l"(c))
#define UNPACKF2(lo, hi, s) \
    asm("mov.b64 {%0, %1}, %2;" : "=f"(lo), "=f"(hi) : "l"(s))

// ---- Pre-kernel 1: weights transpose ----
__global__ void transpose_w_kernel(const float* __restrict__ Wg)
{
    int g = blockIdx.x * blockDim.x + threadIdx.x;
    if (g < COUTC * CIN * 27) {
        int cout = g / (CIN * 27);
        int rem  = g % (CIN * 27);
        int cin  = rem / 27;
        int k    = rem % 27;
        g_wt[(cin * 9 + k / 3) * 48 + (k % 3) * 16 + cout] = Wg[g];
    }
}

// ---- Pre-kernel 2: pad input into g_pad (zero borders) ----
__global__ void pad_x_kernel(const float* __restrict__ X)
{
    size_t i = (size_t)blockIdx.x * blockDim.x + threadIdx.x;
    if (i >= PAD_TOTAL) return;
    int px = (int)(i % PX);
    size_t t = i / PX;
    int py = (int)(t % PY);
    size_t t2 = t / PY;
    int pz = (int)(t2 % PZ);
    int c  = (int)(t2 / PZ);            // b*CIN + cin, matches X channel order
    int gx = px - 2, gy = py - 1, gz = pz - 1;
    float v = 0.0f;
    if ((unsigned)gx < SDIM && (unsigned)gy < SDIM && (unsigned)gz < SDIM)
        v = X[(((size_t)c * SDIM + gz) * SDIM + gy) * SDIM + gx];
    g_pad[i] = v;
}

// ---- Main conv: no smem tile, no barriers; direct LDG.128 input reads ----
__global__ void __launch_bounds__(NTHREADS, 6)
conv3d_kernel(const float* __restrict__ Bias, float* __restrict__ Out)
{
    const int tid = threadIdx.x;
    const int tx  = tid & (TXT - 1);        // 0..7
    const int ty  = (tid >> 3) & (TY - 1);  // 0..3
    const int cg  = tid >> 5;               // warp id = cout group 0..3

    const int z  = blockIdx.x;
    const int y0 = blockIdx.y * TY;
    const int b  = blockIdx.z;

    // Base of this thread's x window in padded coords: need px 8tx+1 .. 8tx+10,
    // loaded as 3 aligned float4 at px 8tx, 8tx+4, 8tx+8 (floats f0..f11, use f1..f10)
    const int pxb = tx * XPT;

    unsigned long long accd[2][XPT];
#pragma unroll
    for (int cp = 0; cp < 2; ++cp)
#pragma unroll
        for (int j = 0; j < XPT; ++j) accd[cp][j] = 0ull;

    const float* padb = g_pad + (size_t)(b * CIN) * PCHAN;

#pragma unroll 1
    for (int cin = 0; cin < CIN; ++cin) {
        const float* pc  = padb + (size_t)cin * PCHAN;
        const float* wci = g_wt + cin * (9 * 48) + cg * CPT;

#pragma unroll
        for (int kd = 0; kd < 3; ++kd) {
#pragma unroll
            for (int kh = 0; kh < 3; ++kh) {
                // input row: padded plane z+kd, row y0+ty+kh (always in-bounds)
                const float* rowp = pc + ((size_t)(z + kd) * PY + (y0 + ty + kh)) * PX + pxb;
                float4 q0 = __ldg(reinterpret_cast<const float4*>(rowp));
                float4 q1 = __ldg(reinterpret_cast<const float4*>(rowp + 4));
                float4 q2 = __ldg(reinterpret_cast<const float4*>(rowp + 8));

                // dup[k] = (v_k, v_k), v_k = f[k+1], k = 0..9
                unsigned long long dup[10];
                PACKF2(dup[0], q0.y, q0.y);
                PACKF2(dup[1], q0.z, q0.z);
                PACKF2(dup[2], q0.w, q0.w);
                PACKF2(dup[3], q1.x, q1.x);
                PACKF2(dup[4], q1.y, q1.y);
                PACKF2(dup[5], q1.z, q1.z);
                PACKF2(dup[6], q1.w, q1.w);
                PACKF2(dup[7], q2.x, q2.x);
                PACKF2(dup[8], q2.y, q2.y);
                PACKF2(dup[9], q2.z, q2.z);

                // weights: one LDG.128 broadcast per kw
                const float* wp = wci + (kd * 3 + kh) * 48;
                unsigned long long wA[3], wB[3];
#pragma unroll
                for (int kw = 0; kw < 3; ++kw) {
                    ulonglong2 q = __ldg(reinterpret_cast<const ulonglong2*>(wp + kw * 16));
                    wA[kw] = q.x;
                    wB[kw] = q.y;
                }

#pragma unroll
                for (int kw = 0; kw < 3; ++kw)
#pragma unroll
                    for (int j = 0; j < XPT; ++j) {
                        FMAF2(accd[0][j], dup[j + kw], wA[kw], accd[0][j]);
                        FMAF2(accd[1][j], dup[j + kw], wB[kw], accd[1][j]);
                    }
            }
        }
    }

    // ---- Epilogue ----
    const int x0 = tx * XPT;
    const int y  = y0 + ty;
#pragma unroll
    for (int cp = 0; cp < 2; ++cp) {
        float o0[XPT], o1[XPT];
#pragma unroll
        for (int j = 0; j < XPT; ++j) UNPACKF2(o0[j], o1[j], accd[cp][j]);

        const int c0 = cg * CPT + 2 * cp;
        const float b0 = __ldg(Bias + c0);
        const float b1 = __ldg(Bias + c0 + 1);

        float* op0 = Out + ((((size_t)b * COUTC + c0)     * SDIM + z) * SDIM + y) * SDIM + x0;
        float* op1 = Out + ((((size_t)b * COUTC + c0 + 1) * SDIM + z) * SDIM + y) * SDIM + x0;

        reinterpret_cast<float4*>(op0)[0] = make_float4(o0[0] + b0, o0[1] + b0, o0[2] + b0, o0[3] + b0);
        reinterpret_cast<float4*>(op0)[1] = make_float4(o0[4] + b0, o0[5] + b0, o0[6] + b0, o0[7] + b0);
        reinterpret_cast<float4*>(op1)[0] = make_float4(o1[0] + b1, o1[1] + b1, o1[2] + b1, o1[3] + b1);
        reinterpret_cast<float4*>(op1)[1] = make_float4(o1[4] + b1, o1[5] + b1, o1[6] + b1, o1[7] + b1);
    }
}

extern "C" void kernel_launch(void* const* d_in, const int* in_sizes, int n_in,
                              void* d_out, int out_size)
{
    const float* x    = (const float*)d_in[0];
    const float* w    = (const float*)d_in[1];
    const float* bias = (const float*)d_in[2];
    float* out        = (float*)d_out;

    transpose_w_kernel<<<(COUTC * CIN * 27 + 255) / 256, 256>>>(w);
    pad_x_kernel<<<(int)((PAD_TOTAL + 255) / 256), 256>>>(x);

    dim3 grid(SDIM, SDIM / TY, BATCH);
    conv3d_kernel<<<grid, NTHREADS>>>(bias, out);
}

// round 11
// speedup vs baseline: 1.0024x; 1.0024x over previous
#include <cuda_runtime.h>
#include <cstdint>

// Problem constants
#define SDIM   64
#define CIN    16
#define COUTC  16
#define BATCH  4

// Tiling (R8 shape: 16 couts per block, 4 per thread, 8 x per thread)
#define TY         4
#define TXT        8
#define XPT        8
#define CPT        4
#define NTHREADS 128

// Padded input scratch: [b*16+cin][pz 66][py 66][px 68], zero borders
#define PX 68
#define PY 66
#define PZ 66
#define PPLANE   (PY * PX)            // 4488
#define PCHAN    (PZ * PPLANE)        // 296208
#define PAD_TOTAL ((size_t)BATCH * CIN * PCHAN)   // 18,957,312 floats

__device__ __align__(16) float g_pad[PAD_TOTAL];

// Transposed weights: [(cin*3+kd)*3+kh][kw*16 + cout]
#define WT_ELEMS (CIN * 9 * 48)
__device__ __align__(16) float g_wt[WT_ELEMS];

#define PACKF2(d, lo, hi) \
    asm("mov.b64 %0, {%1, %2};" : "=l"(d) : "f"(lo), "f"(hi))
#define FMAF2(d, a, b, c) \
    asm("fma.rn.f32x2 %0, %1, %2, %3;" : "=l"(d) : "l"(a), "l"(b), "l"(c))
#define UNPACKF2(lo, hi, s) \
    asm("mov.b64 {%0, %1}, %2;" : "=f"(lo), "=f"(hi) : "l"(s))

// ---- Pre-kernel 1: weights transpose ----
__global__ void transpose_w_kernel(const float* __restrict__ Wg)
{
    int g = blockIdx.x * blockDim.x + threadIdx.x;
    if (g < COUTC * CIN * 27) {
        int cout = g / (CIN * 27);
        int rem  = g % (CIN * 27);
        int cin  = rem / 27;
        int k    = rem % 27;
        g_wt[(cin * 9 + k / 3) * 48 + (k % 3) * 16 + cout] = Wg[g];
    }
}

// ---- Pre-kernel 2: pad input into g_pad (zero borders) ----
__global__ void pad_x_kernel(const float* __restrict__ X)
{
    size_t i = (size_t)blockIdx.x * blockDim.x + threadIdx.x;
    if (i >= PAD_TOTAL) return;
    int px = (int)(i % PX);
    size_t t = i / PX;
    int py = (int)(t % PY);
    size_t t2 = t / PY;
    int pz = (int)(t2 % PZ);
    int c  = (int)(t2 / PZ);            // b*CIN + cin, matches X channel order
    int gx = px - 2, gy = py - 1, gz = pz - 1;
    float v = 0.0f;
    if ((unsigned)gx < SDIM && (unsigned)gy < SDIM && (unsigned)gz < SDIM)
        v = X[(((size_t)c * SDIM + gz) * SDIM + gy) * SDIM + gx];
    g_pad[i] = v;
}

// ---- Main conv: no smem tile, no barriers; direct LDG.128 input reads ----
__global__ void __launch_bounds__(NTHREADS, 6)
conv3d_kernel(const float* __restrict__ Bias, float* __restrict__ Out)
{
    const int tid = threadIdx.x;
    const int tx  = tid & (TXT - 1);        // 0..7
    const int ty  = (tid >> 3) & (TY - 1);  // 0..3
    const int cg  = tid >> 5;               // warp id = cout group 0..3

    const int z  = blockIdx.x;
    const int y0 = blockIdx.y * TY;
    const int b  = blockIdx.z;

    // Base of this thread's x window in padded coords: need px 8tx+1 .. 8tx+10,
    // loaded as 3 aligned float4 at px 8tx, 8tx+4, 8tx+8 (floats f0..f11, use f1..f10)
    const int pxb = tx * XPT;

    unsigned long long accd[2][XPT];
#pragma unroll
    for (int cp = 0; cp < 2; ++cp)
#pragma unroll
        for (int j = 0; j < XPT; ++j) accd[cp][j] = 0ull;

    const float* padb = g_pad + (size_t)(b * CIN) * PCHAN;

#pragma unroll 1
    for (int cin = 0; cin < CIN; ++cin) {
        const float* pc  = padb + (size_t)cin * PCHAN;
        const float* wci = g_wt + cin * (9 * 48) + cg * CPT;

#pragma unroll
        for (int kd = 0; kd < 3; ++kd) {
#pragma unroll
            for (int kh = 0; kh < 3; ++kh) {
                // input row: padded plane z+kd, row y0+ty+kh (always in-bounds)
                const float* rowp = pc + ((size_t)(z + kd) * PY + (y0 + ty + kh)) * PX + pxb;
                float4 q0 = __ldg(reinterpret_cast<const float4*>(rowp));
                float4 q1 = __ldg(reinterpret_cast<const float4*>(rowp + 4));
                float4 q2 = __ldg(reinterpret_cast<const float4*>(rowp + 8));

                // dup[k] = (v_k, v_k), v_k = f[k+1], k = 0..9
                unsigned long long dup[10];
                PACKF2(dup[0], q0.y, q0.y);
                PACKF2(dup[1], q0.z, q0.z);
                PACKF2(dup[2], q0.w, q0.w);
                PACKF2(dup[3], q1.x, q1.x);
                PACKF2(dup[4], q1.y, q1.y);
                PACKF2(dup[5], q1.z, q1.z);
                PACKF2(dup[6], q1.w, q1.w);
                PACKF2(dup[7], q2.x, q2.x);
                PACKF2(dup[8], q2.y, q2.y);
                PACKF2(dup[9], q2.z, q2.z);

                // weights: one LDG.128 broadcast per kw
                const float* wp = wci + (kd * 3 + kh) * 48;
                unsigned long long wA[3], wB[3];
#pragma unroll
                for (int kw = 0; kw < 3; ++kw) {
                    ulonglong2 q = __ldg(reinterpret_cast<const ulonglong2*>(wp + kw * 16));
                    wA[kw] = q.x;
                    wB[kw] = q.y;
                }

#pragma unroll
                for (int kw = 0; kw < 3; ++kw)
#pragma unroll
                    for (int j = 0; j < XPT; ++j) {
                        FMAF2(accd[0][j], dup[j + kw], wA[kw], accd[0][j]);
                        FMAF2(accd[1][j], dup[j + kw], wB[kw], accd[1][j]);
                    }
            }
        }
    }

    // ---- Epilogue ----
    const int x0 = tx * XPT;
    const int y  = y0 + ty;
#pragma unroll
    for (int cp = 0; cp < 2; ++cp) {
        float o0[XPT], o1[XPT];
#pragma unroll
        for (int j = 0; j < XPT; ++j) UNPACKF2(o0[j], o1[j], accd[cp][j]);

        const int c0 = cg * CPT + 2 * cp;
        const float b0 = __ldg(Bias + c0);
        const float b1 = __ldg(Bias + c0 + 1);

        float* op0 = Out + ((((size_t)b * COUTC + c0)     * SDIM + z) * SDIM + y) * SDIM + x0;
        float* op1 = Out + ((((size_t)b * COUTC + c0 + 1) * SDIM + z) * SDIM + y) * SDIM + x0;

        reinterpret_cast<float4*>(op0)[0] = make_float4(o0[0] + b0, o0[1] + b0, o0[2] + b0, o0[3] + b0);
        reinterpret_cast<float4*>(op0)[1] = make_float4(o0[4] + b0, o0[5] + b0, o0[6] + b0, o0[7] + b0);
        reinterpret_cast<float4*>(op1)[0] = make_float4(o1[0] + b1, o1[1] + b1, o1[2] + b1, o1[3] + b1);
        reinterpret_cast<float4*>(op1)[1] = make_float4(o1[4] + b1, o1[5] + b1, o1[6] + b1, o1[7] + b1);
    }
}

extern "C" void kernel_launch(void* const* d_in, const int* in_sizes, int n_in,
                              void* d_out, int out_size)
{
    const float* x    = (const float*)d_in[0];
    const float* w    = (const float*)d_in[1];
    const float* bias = (const float*)d_in[2];
    float* out        = (float*)d_out;

    transpose_w_kernel<<<(COUTC * CIN * 27 + 255) / 256, 256>>>(w);
    pad_x_kernel<<<(int)((PAD_TOTAL + 255) / 256), 256>>>(x);

    dim3 grid(SDIM, SDIM / TY, BATCH);
    conv3d_kernel<<<grid, NTHREADS>>>(bias, out);
}

// round 14
// speedup vs baseline: 1.3005x; 1.2974x over previous
#include <cuda_runtime.h>
#include <cstdint>

// Problem constants
#define SDIM   64
#define CIN    16
#define COUTC  16
#define BATCH  4
#define NT     256

// Slab: 1188 rows ((3z * 6y) * 66 px), each row = 16 cin tf32 + 4 pad words.
// Row stride 20 words -> lane bank = (20*(lid>>2) + lid%4) mod 32, all distinct.
#define SROW_W      20
#define SLAB_ROWS   1188
#define SLAB_WORDS  (SLAB_ROWS * SROW_W)          // 23760
// B tiles: [27 taps][16 cout][20 words (16 cin tf32 + 4 pad)]
#define B_WOFF      SLAB_WORDS
#define B_WORDS     (27 * 16 * SROW_W)            // 8640
#define SMEM_TOTAL  ((SLAB_WORDS + B_WORDS) * 4)  // 129600 bytes

__device__ __align__(16) uint32_t g_B[B_WORDS];

#define CVT_TF32(d, f) asm("cvt.rna.tf32.f32 %0, %1;" : "=r"(d) : "f"(f))

// m16n8k8 tf32 MMA (sm_80+, compiles for plain sm_103 target)
#define MMA_TF32(d, a0, a1, a2, a3, b0, b1)                                   \
    asm volatile("mma.sync.aligned.m16n8k8.row.col.f32.tf32.tf32.f32 "        \
                 "{%0,%1,%2,%3}, {%4,%5,%6,%7}, {%8,%9}, {%0,%1,%2,%3};"      \
                 : "+f"((d)[0]), "+f"((d)[1]), "+f"((d)[2]), "+f"((d)[3])     \
                 : "r"(a0), "r"(a1), "r"(a2), "r"(a3), "r"(b0), "r"(b1))

__device__ __forceinline__ uint32_t smem_u32(const void* p) {
    return (uint32_t)__cvta_generic_to_shared(p);
}

// ---- Pre-kernel: tf32-convert weights into padded B image ----
// g_B[tap][n][wd]: wd<16 -> tf32(W[n][wd][tap]) ; wd>=16 pad = 0
__global__ void prebuild_b_kernel(const float* __restrict__ Wg)
{
    int e = blockIdx.x * blockDim.x + threadIdx.x;
    if (e >= B_WORDS) return;
    int tap = e / (16 * SROW_W);
    int r   = e % (16 * SROW_W);
    int n   = r / SROW_W;
    int wd  = r % SROW_W;
    uint32_t h = 0;
    if (wd < 16) {
        float v = Wg[((size_t)n * CIN + wd) * 27 + tap];
        CVT_TF32(h, v);
    }
    g_B[e] = h;
}

// ---- Main kernel: warp-level TF32 MMA implicit conv ----
__global__ void __launch_bounds__(NT)
conv3d_mma_kernel(const float* __restrict__ X,
                  const float* __restrict__ Bias,
                  float* __restrict__ Out)
{
    extern __shared__ __align__(16) uint32_t smw[];
    const int tid = threadIdx.x;
    const int wid = tid >> 5;
    const int lid = tid & 31;
    const int g   = lid >> 2;     // groupID  (fragment row base)
    const int t   = lid & 3;      // threadID_in_group (fragment col base)

    const int z  = blockIdx.x;
    const int y0 = blockIdx.y * 4;
    const int b  = blockIdx.z;

    // ---- B tiles: cp.async the prebuilt image verbatim ----
    for (int i = tid; i < B_WORDS / 4; i += NT) {
        uint32_t dst = smem_u32(smw + B_WOFF + i * 4);
        asm volatile("cp.async.ca.shared.global [%0], [%1], 16;"
                     :: "r"(dst), "l"((const char*)g_B + i * 16));
    }
    asm volatile("cp.async.commit_group;");

    // ---- Slab fill: conflict-free STS.32 pattern (lanes = 8 rows x 4 cols) ----
    const float* Xb = X + (size_t)b * CIN * (SDIM * SDIM * SDIM);
#pragma unroll 1
    for (int step = 0; step < 19; ++step) {
        int row = step * 64 + wid * 8 + g;
        if (row < SLAB_ROWS) {
            int zy = row / 66, px = row - zy * 66;
            int zp = zy / 6,  yp = zy - zp * 6;
            int gz = z + zp - 1, gy = y0 + yp - 1, gx = px - 1;
            bool valid = ((unsigned)gz < SDIM) && ((unsigned)gy < SDIM) &&
                         ((unsigned)gx < SDIM);
#pragma unroll
            for (int j = 0; j < 4; ++j) {
                int c = t + 4 * j;
                float v = 0.0f;
                if (valid)
                    v = __ldg(Xb + ((size_t)c * SDIM * SDIM * SDIM) +
                              ((size_t)gz * SDIM + gy) * SDIM + gx);
                uint32_t h; CVT_TF32(h, v);
                smw[row * SROW_W + c] = h;
            }
        }
    }

    asm volatile("cp.async.wait_group 0;");
    __syncthreads();

    // ---- Compute: warp = 16 x (x0) x 16 cout x 2 y (ypair) ----
    const int xg    = wid & 3;
    const int ypair = wid >> 2;
    const int x0    = xg * 16;

    float d[2][2][4];   // [yy][n-half][frag]
#pragma unroll
    for (int yy = 0; yy < 2; ++yy)
#pragma unroll
        for (int nh = 0; nh < 2; ++nh)
#pragma unroll
            for (int r = 0; r < 4; ++r) d[yy][nh][r] = 0.0f;

#pragma unroll 1
    for (int kd = 0; kd < 3; ++kd) {
#pragma unroll
        for (int kh = 0; kh < 3; ++kh) {
#pragma unroll
            for (int kw = 0; kw < 3; ++kw) {
                const int tap = (kd * 3 + kh) * 3 + kw;

                // B fragments for both n-halves (reused across both y rows)
                uint32_t bw[2][4];
#pragma unroll
                for (int nh = 0; nh < 2; ++nh) {
                    const uint32_t* bp = smw + B_WOFF + tap * (16 * SROW_W) +
                                         (nh * 8 + g) * SROW_W + t;
                    bw[nh][0] = bp[0];   // kk = t      (chunk0 b0)
                    bw[nh][1] = bp[4];   // kk = t+4    (chunk0 b1)
                    bw[nh][2] = bp[8];   // kk = t+8    (chunk1 b0)
                    bw[nh][3] = bp[12];  // kk = t+12   (chunk1 b1)
                }

#pragma unroll
                for (int yy = 0; yy < 2; ++yy) {
                    const int yo = ypair * 2 + yy;
                    const int s  = (kd * 6 + yo + kh) * 66 + kw + x0;
                    const uint32_t* ap = smw + (s + g) * SROW_W + t;
                    uint32_t a0 = ap[0],   a1 = ap[4];        // row g  : cin t, t+4
                    uint32_t a2 = ap[8],   a3 = ap[12];       // row g  : cin t+8, t+12
                    uint32_t a4 = ap[160], a5 = ap[164];      // row g+8: cin t, t+4
                    uint32_t a6 = ap[168], a7 = ap[172];      // row g+8: cin t+8, t+12

                    // chunk0: cins 0-7 ; frag order {(g,t),(g+8,t),(g,t+4),(g+8,t+4)}
                    MMA_TF32(d[yy][0], a0, a4, a1, a5, bw[0][0], bw[0][1]);
                    MMA_TF32(d[yy][1], a0, a4, a1, a5, bw[1][0], bw[1][1]);
                    // chunk1: cins 8-15
                    MMA_TF32(d[yy][0], a2, a6, a3, a7, bw[0][2], bw[0][3]);
                    MMA_TF32(d[yy][1], a2, a6, a3, a7, bw[1][2], bw[1][3]);
                }
            }
        }
    }

    // ---- Epilogue: D frag -> global, + bias ----
    const size_t COSTRIDE = (size_t)SDIM * SDIM * SDIM;
#pragma unroll
    for (int yy = 0; yy < 2; ++yy) {
        const int y = y0 + ypair * 2 + yy;
#pragma unroll
        for (int nh = 0; nh < 2; ++nh) {
            const int c0 = nh * 8 + 2 * t;
            const float bv0 = __ldg(Bias + c0);
            const float bv1 = __ldg(Bias + c0 + 1);
            float* o0 = Out + (((size_t)(b * COUTC + c0) * SDIM + z) * SDIM + y) * SDIM + x0;
            float* o1 = o0 + COSTRIDE;
            o0[g]     = d[yy][nh][0] + bv0;   // (row g,   col 2t)
            o1[g]     = d[yy][nh][1] + bv1;   // (row g,   col 2t+1)
            o0[g + 8] = d[yy][nh][2] + bv0;   // (row g+8, col 2t)
            o1[g + 8] = d[yy][nh][3] + bv1;   // (row g+8, col 2t+1)
        }
    }
}

extern "C" void kernel_launch(void* const* d_in, const int* in_sizes, int n_in,
                              void* d_out, int out_size)
{
    const float* x    = (const float*)d_in[0];
    const float* w    = (const float*)d_in[1];
    const float* bias = (const float*)d_in[2];
    float* out        = (float*)d_out;

    cudaFuncSetAttribute(conv3d_mma_kernel,
                         cudaFuncAttributeMaxDynamicSharedMemorySize, SMEM_TOTAL);

    prebuild_b_kernel<<<(B_WORDS + NT - 1) / NT, NT>>>(w);

    dim3 grid(SDIM, SDIM / 4, BATCH);
    conv3d_mma_kernel<<<grid, NT, SMEM_TOTAL>>>(x, bias, out);
}

// round 15
// speedup vs baseline: 2.0430x; 1.5710x over previous
#include <cuda_runtime.h>
#include <cstdint>

// Problem constants
#define SDIM   64
#define CIN    16
#define COUTC  16
#define BATCH  4
#define NT     256

// Slab: 1188 rows ((3z * 6y) * 66 px), each row = 16 cin tf32 + 4 pad words.
// Row stride 20 words -> lane bank = (20*(lid>>2) + lid%4) mod 32, all distinct.
#define SROW_W      20
#define SLAB_ROWS   1188
#define SLAB_WORDS  (SLAB_ROWS * SROW_W)          // 23760
#define SMEM_TOTAL  (SLAB_WORDS * 4)              // 95040 bytes -> 2 CTAs/SM

// Per-lane-contiguous B image: [tap][nh][lane][4 words] = 27*2*32*4
#define B2_WORDS (27 * 2 * 32 * 4)

__device__ __align__(16) uint32_t g_B2[B2_WORDS];

#define CVT_TF32(d, f) asm("cvt.rna.tf32.f32 %0, %1;" : "=r"(d) : "f"(f))

// m16n8k8 tf32 MMA (sm_80+, compiles for plain sm_103 target)
#define MMA_TF32(d, a0, a1, a2, a3, b0, b1)                                   \
    asm volatile("mma.sync.aligned.m16n8k8.row.col.f32.tf32.tf32.f32 "        \
                 "{%0,%1,%2,%3}, {%4,%5,%6,%7}, {%8,%9}, {%0,%1,%2,%3};"      \
                 : "+f"((d)[0]), "+f"((d)[1]), "+f"((d)[2]), "+f"((d)[3])     \
                 : "r"(a0), "r"(a1), "r"(a2), "r"(a3), "r"(b0), "r"(b1))

// ---- Pre-kernel: tf32-convert weights into per-lane-contiguous B image ----
// Fragment mapping (validated in R14): lane (g,t), row n = nh*8+g, cin = t+4k.
__global__ void prebuild_b_kernel(const float* __restrict__ Wg)
{
    int e = blockIdx.x * blockDim.x + threadIdx.x;
    if (e >= B2_WORDS) return;
    int tap = e >> 8;              // /256
    int r   = e & 255;
    int nh  = r >> 7;
    int lid = (r >> 2) & 31;
    int k   = r & 3;
    int g   = lid >> 2;
    int t   = lid & 3;
    int n   = nh * 8 + g;
    int cin = t + 4 * k;
    float v = Wg[((size_t)n * CIN + cin) * 27 + tap];
    uint32_t h; CVT_TF32(h, v);
    g_B2[e] = h;
}

// ---- Main kernel: warp-level TF32 MMA implicit conv ----
__global__ void __launch_bounds__(NT, 2)
conv3d_mma_kernel(const float* __restrict__ X,
                  const float* __restrict__ Bias,
                  float* __restrict__ Out)
{
    extern __shared__ __align__(16) uint32_t smw[];
    const int tid = threadIdx.x;
    const int wid = tid >> 5;
    const int lid = tid & 31;
    const int g   = lid >> 2;     // groupID  (fragment row base)
    const int t   = lid & 3;      // threadID_in_group (fragment col base)

    const int z  = blockIdx.x;
    const int y0 = blockIdx.y * 4;
    const int b  = blockIdx.z;

    // ---- Slab fill: conflict-free STS.32 pattern (lanes = 8 rows x 4 cols) ----
    const float* Xb = X + (size_t)b * CIN * (SDIM * SDIM * SDIM);
#pragma unroll 1
    for (int step = 0; step < 19; ++step) {
        int row = step * 64 + wid * 8 + g;
        if (row < SLAB_ROWS) {
            int zy = row / 66, px = row - zy * 66;
            int zp = zy / 6,  yp = zy - zp * 6;
            int gz = z + zp - 1, gy = y0 + yp - 1, gx = px - 1;
            bool valid = ((unsigned)gz < SDIM) && ((unsigned)gy < SDIM) &&
                         ((unsigned)gx < SDIM);
#pragma unroll
            for (int j = 0; j < 4; ++j) {
                int c = t + 4 * j;
                float v = 0.0f;
                if (valid)
                    v = __ldg(Xb + ((size_t)c * SDIM * SDIM * SDIM) +
                              ((size_t)gz * SDIM + gy) * SDIM + gx);
                uint32_t h; CVT_TF32(h, v);
                smw[row * SROW_W + c] = h;
            }
        }
    }
    __syncthreads();

    // ---- Compute: warp = 16 x (x0) x 16 cout x 2 y (ypair) ----
    const int xg    = wid & 3;
    const int ypair = wid >> 2;
    const int x0    = xg * 16;

    float d[2][2][4];   // [yy][n-half][frag]
#pragma unroll
    for (int yy = 0; yy < 2; ++yy)
#pragma unroll
        for (int nh = 0; nh < 2; ++nh)
#pragma unroll
            for (int r = 0; r < 4; ++r) d[yy][nh][r] = 0.0f;

    const uint4* Bimg = reinterpret_cast<const uint4*>(g_B2);

#pragma unroll 1
    for (int kd = 0; kd < 3; ++kd) {
#pragma unroll
        for (int kh = 0; kh < 3; ++kh) {
#pragma unroll
            for (int kw = 0; kw < 3; ++kw) {
                const int tap = (kd * 3 + kh) * 3 + kw;

                // B fragments: 2 coalesced LDG.128 per lane (L1-resident image)
                uint4 b0 = __ldg(Bimg + (tap * 2 + 0) * 32 + lid);
                uint4 b1 = __ldg(Bimg + (tap * 2 + 1) * 32 + lid);

#pragma unroll
                for (int yy = 0; yy < 2; ++yy) {
                    const int yo = ypair * 2 + yy;
                    const int s  = (kd * 6 + yo + kh) * 66 + kw + x0;
                    const uint32_t* ap = smw + (s + g) * SROW_W + t;
                    uint32_t a0 = ap[0],   a1 = ap[4];        // row g  : cin t, t+4
                    uint32_t a2 = ap[8],   a3 = ap[12];       // row g  : cin t+8, t+12
                    uint32_t a4 = ap[160], a5 = ap[164];      // row g+8: cin t, t+4
                    uint32_t a6 = ap[168], a7 = ap[172];      // row g+8: cin t+8, t+12

                    // chunk0: cins 0-7 ; chunk1: cins 8-15
                    MMA_TF32(d[yy][0], a0, a4, a1, a5, b0.x, b0.y);
                    MMA_TF32(d[yy][1], a0, a4, a1, a5, b1.x, b1.y);
                    MMA_TF32(d[yy][0], a2, a6, a3, a7, b0.z, b0.w);
                    MMA_TF32(d[yy][1], a2, a6, a3, a7, b1.z, b1.w);
                }
            }
        }
    }

    // ---- Epilogue: D frag -> global, + bias ----
    const size_t COSTRIDE = (size_t)SDIM * SDIM * SDIM;
#pragma unroll
    for (int yy = 0; yy < 2; ++yy) {
        const int y = y0 + ypair * 2 + yy;
#pragma unroll
        for (int nh = 0; nh < 2; ++nh) {
            const int c0 = nh * 8 + 2 * t;
            const float bv0 = __ldg(Bias + c0);
            const float bv1 = __ldg(Bias + c0 + 1);
            float* o0 = Out + (((size_t)(b * COUTC + c0) * SDIM + z) * SDIM + y) * SDIM + x0;
            float* o1 = o0 + COSTRIDE;
            o0[g]     = d[yy][nh][0] + bv0;   // (row g,   col 2t)
            o1[g]     = d[yy][nh][1] + bv1;   // (row g,   col 2t+1)
            o0[g + 8] = d[yy][nh][2] + bv0;   // (row g+8, col 2t)
            o1[g + 8] = d[yy][nh][3] + bv1;   // (row g+8, col 2t+1)
        }
    }
}

extern "C" void kernel_launch(void* const* d_in, const int* in_sizes, int n_in,
                              void* d_out, int out_size)
{
    const float* x    = (const float*)d_in[0];
    const float* w    = (const float*)d_in[1];
    const float* bias = (const float*)d_in[2];
    float* out        = (float*)d_out;

    cudaFuncSetAttribute(conv3d_mma_kernel,
                         cudaFuncAttributeMaxDynamicSharedMemorySize, SMEM_TOTAL);

    prebuild_b_kernel<<<(B2_WORDS + NT - 1) / NT, NT>>>(w);

    dim3 grid(SDIM, SDIM / 4, BATCH);
    conv3d_mma_kernel<<<grid, NT, SMEM_TOTAL>>>(x, bias, out);
}